// round 7
// baseline (speedup 1.0000x reference)
#include <cuda_runtime.h>
#include <cstdint>

#define M_DIM 4096
#define N_DIM 8192

// ---------------------------------------------------------------------------
// Single fused kernel, redundant-MLP edition.
// Grid: (8, 128) = 1024 blocks x 256 threads.
// Block (bx, by) owns output rows [32*by, 32*by+32) x cols [1024*bx, +1024).
// Each block redundantly: folds W5/b5 through {Wc0, Wc1, bc}; runs the MLP
// for its 32 rows; then streams its 32x1024 sub-slab with st.global.cs.
// Redundancy cost (8x MLP) ~ 240 MFLOP total -- noise. The win: ~6 CTAs/SM
// resident, so store issue saturates DRAM while other CTAs do prologue.
// ---------------------------------------------------------------------------
__global__ __launch_bounds__(256) void fused_kernel(
    const float* __restrict__ noise,
    const float* __restrict__ coords,
    const float* __restrict__ W1, const float* __restrict__ b1,
    const float* __restrict__ W2, const float* __restrict__ b2,
    const float* __restrict__ W3, const float* __restrict__ b3,
    const float* __restrict__ W4, const float* __restrict__ b4,
    const float* __restrict__ W5, const float* __restrict__ b5,
    const float* __restrict__ Wc, const float* __restrict__ bc,
    const float* __restrict__ Wm, const float* __restrict__ bm,
    float* __restrict__ out)
{
    __shared__ float sW1[128 * 32];
    __shared__ float sW2[32 * 32];
    __shared__ float sW3[32 * 32];
    __shared__ float sW4[32 * 32];
    __shared__ float sb[4 * 32];
    __shared__ float sF[3][32];
    __shared__ float sc3[3];
    __shared__ float hbuf[32][33];
    __shared__ float4 sp4[32];

    int tid  = threadIdx.x;
    int lane = tid & 31;
    int wid  = tid >> 5;

    // ---- coords for this block's 1024 cols: fetch early (independent) ----
    int j = blockIdx.x * 1024 + tid * 4;
    float4 ca = *(const float4*)(coords + 2 * j);
    float4 cb = *(const float4*)(coords + 2 * j + 4);

    // ---- Phase 0a: weights -> smem ----
    for (int i = tid; i < 128 * 32; i += 256) sW1[i] = W1[i];
    for (int i = tid; i < 32 * 32; i += 256) {
        sW2[i] = W2[i]; sW3[i] = W3[i]; sW4[i] = W4[i];
    }
    if (tid < 32) {
        sb[tid] = b1[tid]; sb[32 + tid] = b2[tid];
        sb[64 + tid] = b3[tid]; sb[96 + tid] = b4[tid];
    }

    // ---- Phase 0b: fold. F[c][k] = sum_p W5[k,p]*G[c][p]; G={Wc0,Wc1,bc} ----
    if (tid < 96) {
        int k = tid & 31, c = tid >> 5;
        const float* gr = (c == 0) ? Wc : (c == 1) ? (Wc + 256) : bc;
        const float* wr = W5 + k * 256;
        float s0 = 0.f, s1 = 0.f, s2 = 0.f, s3 = 0.f;
        #pragma unroll 16
        for (int p = 0; p < 256; p += 4) {
            s0 = fmaf(wr[p],     gr[p],     s0);
            s1 = fmaf(wr[p + 1], gr[p + 1], s1);
            s2 = fmaf(wr[p + 2], gr[p + 2], s2);
            s3 = fmaf(wr[p + 3], gr[p + 3], s3);
        }
        sF[c][k] = (s0 + s1) + (s2 + s3);
    } else if (tid < 99) {
        int c = tid - 96;
        const float* gr = (c == 0) ? Wc : (c == 1) ? (Wc + 256) : bc;
        float s0 = 0.f, s1 = 0.f, s2 = 0.f, s3 = 0.f;
        #pragma unroll 16
        for (int p = 0; p < 256; p += 4) {
            s0 = fmaf(b5[p],     gr[p],     s0);
            s1 = fmaf(b5[p + 1], gr[p + 1], s1);
            s2 = fmaf(b5[p + 2], gr[p + 2], s2);
            s3 = fmaf(b5[p + 3], gr[p + 3], s3);
        }
        float extra = (c == 0) ? Wm[0] : (c == 1) ? Wm[1] : bm[0];
        sc3[c] = ((s0 + s1) + (s2 + s3)) + extra;
    }
    __syncthreads();

    // ---- Phase 1: MLP, 8 warps x 4 interleaved row chains = 32 rows ----
    int rows0 = blockIdx.y * 32;
    float x[4][4];
    #pragma unroll
    for (int q = 0; q < 4; q++) {
        const float* xr = noise + (rows0 + wid * 4 + q) * 128;
        x[q][0] = xr[lane];      x[q][1] = xr[lane + 32];
        x[q][2] = xr[lane + 64]; x[q][3] = xr[lane + 96];
    }

    float acc[4];
    #pragma unroll
    for (int q = 0; q < 4; q++) acc[q] = sb[lane];
    #pragma unroll
    for (int seg = 0; seg < 4; seg++) {
        #pragma unroll
        for (int k = 0; k < 32; k++) {
            float w = sW1[(seg * 32 + k) * 32 + lane];
            #pragma unroll
            for (int q = 0; q < 4; q++)
                acc[q] = fmaf(__shfl_sync(~0u, x[q][seg], k), w, acc[q]);
        }
    }
    float h[4];
    #pragma unroll
    for (int q = 0; q < 4; q++) h[q] = tanhf(acc[q]);

    #pragma unroll
    for (int L = 0; L < 3; L++) {
        const float* W = (L == 0) ? sW2 : (L == 1) ? sW3 : sW4;
        float nh[4];
        #pragma unroll
        for (int q = 0; q < 4; q++) nh[q] = sb[32 * (L + 1) + lane];
        #pragma unroll
        for (int k = 0; k < 32; k++) {
            float w = W[k * 32 + lane];
            #pragma unroll
            for (int q = 0; q < 4; q++)
                nh[q] = fmaf(__shfl_sync(~0u, h[q], k), w, nh[q]);
        }
        #pragma unroll
        for (int q = 0; q < 4; q++) h[q] = tanhf(nh[q]);
    }
    #pragma unroll
    for (int q = 0; q < 4; q++) hbuf[wid * 4 + q][lane] = h[q];
    __syncthreads();

    // head: p_c(row) = sum_k hbuf[row][k] * F[c][k] + c3[c]
    if (tid < 96) {
        int row = tid & 31, c = tid >> 5;
        float p0 = 0.f, p1 = 0.f;
        #pragma unroll
        for (int k = 0; k < 32; k += 2) {
            p0 = fmaf(hbuf[row][k],     sF[c][k],     p0);
            p1 = fmaf(hbuf[row][k + 1], sF[c][k + 1], p1);
        }
        ((float*)&sp4[row])[c] = (p0 + p1) + sc3[c];
    }
    __syncthreads();

    // ---- Phase 2: stream 32 rows x 1024 cols, evict-first stores ----
    float* op = out + (size_t)rows0 * N_DIM + j;
    #pragma unroll 8
    for (int r = 0; r < 32; r++) {
        float4 P = sp4[r];
        float vx = fmaf(P.x, ca.x, fmaf(P.y, ca.y, P.z));
        float vy = fmaf(P.x, ca.z, fmaf(P.y, ca.w, P.z));
        float vz = fmaf(P.x, cb.x, fmaf(P.y, cb.y, P.z));
        float vw = fmaf(P.x, cb.z, fmaf(P.y, cb.w, P.z));
        asm volatile("st.global.cs.v4.f32 [%0], {%1,%2,%3,%4};"
                     :: "l"(op + (size_t)r * N_DIM),
                        "f"(vx), "f"(vy), "f"(vz), "f"(vw) : "memory");
    }
}

// ---------------------------------------------------------------------------
extern "C" void kernel_launch(void* const* d_in, const int* in_sizes, int n_in,
                              void* d_out, int out_size) {
    const float* noise  = (const float*)d_in[0];
    const float* coords = (const float*)d_in[1];
    const float* W1 = (const float*)d_in[2];  const float* b1 = (const float*)d_in[3];
    const float* W2 = (const float*)d_in[4];  const float* b2 = (const float*)d_in[5];
    const float* W3 = (const float*)d_in[6];  const float* b3 = (const float*)d_in[7];
    const float* W4 = (const float*)d_in[8];  const float* b4 = (const float*)d_in[9];
    const float* W5 = (const float*)d_in[10]; const float* b5 = (const float*)d_in[11];
    const float* Wc = (const float*)d_in[12]; const float* bc = (const float*)d_in[13];
    const float* Wm = (const float*)d_in[14]; const float* bm = (const float*)d_in[15];
    float* out = (float*)d_out;

    dim3 grid(N_DIM / 1024, M_DIM / 32);
    fused_kernel<<<grid, 256>>>(noise, coords,
                                W1, b1, W2, b2, W3, b3, W4, b4, W5, b5,
                                Wc, bc, Wm, bm, out);
}

// round 8
// speedup vs baseline: 1.6883x; 1.6883x over previous
#include <cuda_runtime.h>
#include <cstdint>

#define M_DIM 4096
#define N_DIM 8192

// ---------------------------------------------------------------------------
// Single fused kernel, zero-redundancy MLP edition.
// Grid: 512 blocks x 256 threads. Block b owns rows [8b, 8b+8) x ALL 8192 cols.
// - fold (redundant, tiny): threads <99 fold W5/b5 through {Wc0, Wc1, bc}.
// - MLP: 8 warps, warp w computes row 8b+w (one chain, lane = hidden unit).
// - head: 24 threads -> sp4[8] = (p0, p1, p2) per row.
// - store: 8 chunks x 1024 cols, 8 rows each, plain STG.128 (evict-normal).
// 512 CTAs (~3.5/SM) give enough store concurrency to saturate HBM writes
// while other CTAs run their prologue.
// ---------------------------------------------------------------------------
__global__ __launch_bounds__(256) void fused_kernel(
    const float* __restrict__ noise,
    const float* __restrict__ coords,
    const float* __restrict__ W1, const float* __restrict__ b1,
    const float* __restrict__ W2, const float* __restrict__ b2,
    const float* __restrict__ W3, const float* __restrict__ b3,
    const float* __restrict__ W4, const float* __restrict__ b4,
    const float* __restrict__ W5, const float* __restrict__ b5,
    const float* __restrict__ Wc, const float* __restrict__ bc,
    const float* __restrict__ Wm, const float* __restrict__ bm,
    float* __restrict__ out)
{
    __shared__ float sW1[128 * 32];
    __shared__ float sW2[32 * 32];
    __shared__ float sW3[32 * 32];
    __shared__ float sW4[32 * 32];
    __shared__ float sb[4 * 32];
    __shared__ float sF[3][32];
    __shared__ float sc3[3];
    __shared__ float hbuf[8][33];
    __shared__ float4 sp4[8];

    int tid  = threadIdx.x;
    int lane = tid & 31;
    int wid  = tid >> 5;

    // ---- Phase 0a: weights -> smem ----
    for (int i = tid; i < 128 * 32; i += 256) sW1[i] = W1[i];
    for (int i = tid; i < 32 * 32; i += 256) {
        sW2[i] = W2[i]; sW3[i] = W3[i]; sW4[i] = W4[i];
    }
    if (tid < 32) {
        sb[tid] = b1[tid]; sb[32 + tid] = b2[tid];
        sb[64 + tid] = b3[tid]; sb[96 + tid] = b4[tid];
    }

    // ---- Phase 0b: fold. F[c][k] = sum_p W5[k,p]*G[c][p]; G={Wc0,Wc1,bc} ----
    if (tid < 96) {
        int k = tid & 31, c = tid >> 5;
        const float* gr = (c == 0) ? Wc : (c == 1) ? (Wc + 256) : bc;
        const float* wr = W5 + k * 256;
        float s0 = 0.f, s1 = 0.f, s2 = 0.f, s3 = 0.f;
        #pragma unroll 16
        for (int p = 0; p < 256; p += 4) {
            s0 = fmaf(wr[p],     gr[p],     s0);
            s1 = fmaf(wr[p + 1], gr[p + 1], s1);
            s2 = fmaf(wr[p + 2], gr[p + 2], s2);
            s3 = fmaf(wr[p + 3], gr[p + 3], s3);
        }
        sF[c][k] = (s0 + s1) + (s2 + s3);
    } else if (tid < 99) {
        int c = tid - 96;
        const float* gr = (c == 0) ? Wc : (c == 1) ? (Wc + 256) : bc;
        float s0 = 0.f, s1 = 0.f, s2 = 0.f, s3 = 0.f;
        #pragma unroll 16
        for (int p = 0; p < 256; p += 4) {
            s0 = fmaf(b5[p],     gr[p],     s0);
            s1 = fmaf(b5[p + 1], gr[p + 1], s1);
            s2 = fmaf(b5[p + 2], gr[p + 2], s2);
            s3 = fmaf(b5[p + 3], gr[p + 3], s3);
        }
        float extra = (c == 0) ? Wm[0] : (c == 1) ? Wm[1] : bm[0];
        sc3[c] = ((s0 + s1) + (s2 + s3)) + extra;
    }
    __syncthreads();

    // ---- Phase 1: MLP, warp w -> row rows0 + w (single chain) ----
    int rows0 = blockIdx.x * 8;
    const float* xr = noise + (rows0 + wid) * 128;
    float x0 = xr[lane], x1 = xr[lane + 32], x2 = xr[lane + 64], x3 = xr[lane + 96];

    float a0 = sb[lane], a1 = 0.f, a2 = 0.f, a3 = 0.f;
    #pragma unroll
    for (int k = 0; k < 32; k++) {
        a0 = fmaf(__shfl_sync(~0u, x0, k), sW1[k * 32 + lane],         a0);
        a1 = fmaf(__shfl_sync(~0u, x1, k), sW1[(k + 32) * 32 + lane],  a1);
        a2 = fmaf(__shfl_sync(~0u, x2, k), sW1[(k + 64) * 32 + lane],  a2);
        a3 = fmaf(__shfl_sync(~0u, x3, k), sW1[(k + 96) * 32 + lane],  a3);
    }
    float h = tanhf((a0 + a1) + (a2 + a3));

    #pragma unroll
    for (int L = 0; L < 3; L++) {
        const float* W = (L == 0) ? sW2 : (L == 1) ? sW3 : sW4;
        float a = sb[32 * (L + 1) + lane];
        #pragma unroll
        for (int k = 0; k < 32; k++)
            a = fmaf(__shfl_sync(~0u, h, k), W[k * 32 + lane], a);
        h = tanhf(a);
    }
    hbuf[wid][lane] = h;
    __syncthreads();

    // head: p_c(row) = sum_k hbuf[row][k] * F[c][k] + c3[c]   (24 threads)
    if (tid < 24) {
        int row = tid & 7, c = tid >> 3;
        float p0 = 0.f, p1 = 0.f;
        #pragma unroll
        for (int k = 0; k < 32; k += 2) {
            p0 = fmaf(hbuf[row][k],     sF[c][k],     p0);
            p1 = fmaf(hbuf[row][k + 1], sF[c][k + 1], p1);
        }
        ((float*)&sp4[row])[c] = (p0 + p1) + sc3[c];
    }
    __syncthreads();

    // ---- Phase 2: stream 8 rows x 8192 cols ----
    float* oslab = out + (size_t)rows0 * N_DIM;
    #pragma unroll
    for (int chunk = 0; chunk < 8; chunk++) {
        int j = chunk * 1024 + tid * 4;
        float4 ca = *(const float4*)(coords + 2 * j);
        float4 cb = *(const float4*)(coords + 2 * j + 4);
        float* op = oslab + j;
        #pragma unroll
        for (int r = 0; r < 8; r++) {
            float4 P = sp4[r];
            float4 v;
            v.x = fmaf(P.x, ca.x, fmaf(P.y, ca.y, P.z));
            v.y = fmaf(P.x, ca.z, fmaf(P.y, ca.w, P.z));
            v.z = fmaf(P.x, cb.x, fmaf(P.y, cb.y, P.z));
            v.w = fmaf(P.x, cb.z, fmaf(P.y, cb.w, P.z));
            *(float4*)(op + (size_t)r * N_DIM) = v;
        }
    }
}

// ---------------------------------------------------------------------------
extern "C" void kernel_launch(void* const* d_in, const int* in_sizes, int n_in,
                              void* d_out, int out_size) {
    const float* noise  = (const float*)d_in[0];
    const float* coords = (const float*)d_in[1];
    const float* W1 = (const float*)d_in[2];  const float* b1 = (const float*)d_in[3];
    const float* W2 = (const float*)d_in[4];  const float* b2 = (const float*)d_in[5];
    const float* W3 = (const float*)d_in[6];  const float* b3 = (const float*)d_in[7];
    const float* W4 = (const float*)d_in[8];  const float* b4 = (const float*)d_in[9];
    const float* W5 = (const float*)d_in[10]; const float* b5 = (const float*)d_in[11];
    const float* Wc = (const float*)d_in[12]; const float* bc = (const float*)d_in[13];
    const float* Wm = (const float*)d_in[14]; const float* bm = (const float*)d_in[15];
    float* out = (float*)d_out;

    fused_kernel<<<M_DIM / 8, 256>>>(noise, coords,
                                     W1, b1, W2, b2, W3, b3, W4, b4, W5, b5,
                                     Wc, bc, Wm, bm, out);
}

// round 9
// speedup vs baseline: 2.2291x; 1.3203x over previous
#include <cuda_runtime.h>
#include <cstdint>

#define M_DIM 4096
#define N_DIM 8192

// Per-row coefficients: out[i,j] = P[i].x*c0_j + P[i].y*c1_j + P[i].z
__device__ __align__(16) float4 g_P[M_DIM];

// ---------------------------------------------------------------------------
// Kernel 1: Branch MLP + fold, fused. 256 blocks x 256 threads.
// Block b owns rows [16b, 16b+16): 8 warps x 2 interleaved row chains.
// Fold (redundant per block, 3 warps' worth of work): F[3][32], c3[3].
// ---------------------------------------------------------------------------
__global__ __launch_bounds__(256) void branch_kernel(
    const float* __restrict__ noise,
    const float* __restrict__ W1, const float* __restrict__ b1,
    const float* __restrict__ W2, const float* __restrict__ b2,
    const float* __restrict__ W3, const float* __restrict__ b3,
    const float* __restrict__ W4, const float* __restrict__ b4,
    const float* __restrict__ W5, const float* __restrict__ b5,
    const float* __restrict__ Wc, const float* __restrict__ bc,
    const float* __restrict__ Wm, const float* __restrict__ bm)
{
    __shared__ float sW1[128 * 32];
    __shared__ float sW2[32 * 32];
    __shared__ float sW3[32 * 32];
    __shared__ float sW4[32 * 32];
    __shared__ float sb[4 * 32];
    __shared__ float sF[3][32];
    __shared__ float sc3[3];

    int tid  = threadIdx.x;
    int lane = tid & 31;
    int wid  = tid >> 5;

    // ---- weights -> smem ----
    for (int i = tid; i < 128 * 32; i += 256) sW1[i] = W1[i];
    for (int i = tid; i < 32 * 32; i += 256) {
        sW2[i] = W2[i]; sW3[i] = W3[i]; sW4[i] = W4[i];
    }
    if (tid < 32) {
        sb[tid] = b1[tid]; sb[32 + tid] = b2[tid];
        sb[64 + tid] = b3[tid]; sb[96 + tid] = b4[tid];
    }

    // ---- fold: F[c][k] = sum_p W5[k,p]*G[c][p]; G = {Wc0, Wc1, bc} ----
    if (tid < 96) {
        int k = tid & 31, c = tid >> 5;
        const float* gr = (c == 0) ? Wc : (c == 1) ? (Wc + 256) : bc;
        const float* wr = W5 + k * 256;
        float s0 = 0.f, s1 = 0.f, s2 = 0.f, s3 = 0.f;
        #pragma unroll 16
        for (int p = 0; p < 256; p += 4) {
            s0 = fmaf(wr[p],     gr[p],     s0);
            s1 = fmaf(wr[p + 1], gr[p + 1], s1);
            s2 = fmaf(wr[p + 2], gr[p + 2], s2);
            s3 = fmaf(wr[p + 3], gr[p + 3], s3);
        }
        sF[c][k] = (s0 + s1) + (s2 + s3);
    } else if (tid < 99) {
        int c = tid - 96;
        const float* gr = (c == 0) ? Wc : (c == 1) ? (Wc + 256) : bc;
        float s0 = 0.f, s1 = 0.f, s2 = 0.f, s3 = 0.f;
        #pragma unroll 16
        for (int p = 0; p < 256; p += 4) {
            s0 = fmaf(b5[p],     gr[p],     s0);
            s1 = fmaf(b5[p + 1], gr[p + 1], s1);
            s2 = fmaf(b5[p + 2], gr[p + 2], s2);
            s3 = fmaf(b5[p + 3], gr[p + 3], s3);
        }
        float extra = (c == 0) ? Wm[0] : (c == 1) ? Wm[1] : bm[0];
        sc3[c] = ((s0 + s1) + (s2 + s3)) + extra;
    }
    __syncthreads();

    // ---- MLP: two interleaved rows per warp ----
    int rowA = blockIdx.x * 16 + wid;
    int rowB = rowA + 8;

    const float* xa = noise + rowA * 128;
    const float* xb = noise + rowB * 128;
    float xa0 = xa[lane], xa1 = xa[lane + 32], xa2 = xa[lane + 64], xa3 = xa[lane + 96];
    float xb0 = xb[lane], xb1 = xb[lane + 32], xb2 = xb[lane + 64], xb3 = xb[lane + 96];

    float aa0 = sb[lane], aa1 = 0.f, aa2 = 0.f, aa3 = 0.f;
    float ba0 = sb[lane], ba1 = 0.f, ba2 = 0.f, ba3 = 0.f;
    #pragma unroll
    for (int k = 0; k < 32; k++) {
        float w0 = sW1[k * 32 + lane];
        float w1 = sW1[(k + 32) * 32 + lane];
        float w2 = sW1[(k + 64) * 32 + lane];
        float w3 = sW1[(k + 96) * 32 + lane];
        aa0 = fmaf(__shfl_sync(~0u, xa0, k), w0, aa0);
        ba0 = fmaf(__shfl_sync(~0u, xb0, k), w0, ba0);
        aa1 = fmaf(__shfl_sync(~0u, xa1, k), w1, aa1);
        ba1 = fmaf(__shfl_sync(~0u, xb1, k), w1, ba1);
        aa2 = fmaf(__shfl_sync(~0u, xa2, k), w2, aa2);
        ba2 = fmaf(__shfl_sync(~0u, xb2, k), w2, ba2);
        aa3 = fmaf(__shfl_sync(~0u, xa3, k), w3, aa3);
        ba3 = fmaf(__shfl_sync(~0u, xb3, k), w3, ba3);
    }
    float hA = tanhf((aa0 + aa1) + (aa2 + aa3));
    float hB = tanhf((ba0 + ba1) + (ba2 + ba3));

    #pragma unroll
    for (int L = 0; L < 3; L++) {
        const float* W = (L == 0) ? sW2 : (L == 1) ? sW3 : sW4;
        float a = sb[32 * (L + 1) + lane];
        float b = a;
        #pragma unroll
        for (int k = 0; k < 32; k++) {
            float w = W[k * 32 + lane];
            a = fmaf(__shfl_sync(~0u, hA, k), w, a);
            b = fmaf(__shfl_sync(~0u, hB, k), w, b);
        }
        hA = tanhf(a);
        hB = tanhf(b);
    }

    // ---- head: warp-reduce h . F[c] for both rows ----
    float F0 = sF[0][lane], F1 = sF[1][lane], F2 = sF[2][lane];
    float pa0 = hA * F0, pa1 = hA * F1, pa2 = hA * F2;
    float pb0 = hB * F0, pb1 = hB * F1, pb2 = hB * F2;
    #pragma unroll
    for (int off = 16; off; off >>= 1) {
        pa0 += __shfl_xor_sync(~0u, pa0, off);
        pa1 += __shfl_xor_sync(~0u, pa1, off);
        pa2 += __shfl_xor_sync(~0u, pa2, off);
        pb0 += __shfl_xor_sync(~0u, pb0, off);
        pb1 += __shfl_xor_sync(~0u, pb1, off);
        pb2 += __shfl_xor_sync(~0u, pb2, off);
    }
    if (lane == 0) {
        g_P[rowA] = make_float4(pa0 + sc3[0], pa1 + sc3[1], pa2 + sc3[2], 0.f);
        g_P[rowB] = make_float4(pb0 + sc3[0], pb1 + sc3[1], pb2 + sc3[2], 0.f);
    }
}

// ---------------------------------------------------------------------------
// Kernel 2: writer. Grid (8, 128) = 1024 blocks x 256 threads.
// Block (bx, by): rows [32*by, +32) x cols [1024*bx, +1024).
// out[i][j] = P[i].x*c0_j + P[i].y*c1_j + P[i].z, pure coalesced STG.128.
// ---------------------------------------------------------------------------
__global__ __launch_bounds__(256) void out_kernel(
    const float* __restrict__ coords, float* __restrict__ out)
{
    __shared__ float4 sP[32];
    int tid = threadIdx.x;
    int r0  = blockIdx.y * 32;
    if (tid < 32) sP[tid] = g_P[r0 + tid];

    int j = blockIdx.x * 1024 + tid * 4;
    float4 ca = *(const float4*)(coords + 2 * j);
    float4 cb = *(const float4*)(coords + 2 * j + 4);
    __syncthreads();

    float* orow = out + (size_t)r0 * N_DIM + j;
    #pragma unroll 8
    for (int r = 0; r < 32; r++) {
        float4 P = sP[r];
        float4 v;
        v.x = fmaf(P.x, ca.x, fmaf(P.y, ca.y, P.z));
        v.y = fmaf(P.x, ca.z, fmaf(P.y, ca.w, P.z));
        v.z = fmaf(P.x, cb.x, fmaf(P.y, cb.y, P.z));
        v.w = fmaf(P.x, cb.z, fmaf(P.y, cb.w, P.z));
        *(float4*)(orow + (size_t)r * N_DIM) = v;
    }
}

// ---------------------------------------------------------------------------
extern "C" void kernel_launch(void* const* d_in, const int* in_sizes, int n_in,
                              void* d_out, int out_size) {
    const float* noise  = (const float*)d_in[0];
    const float* coords = (const float*)d_in[1];
    const float* W1 = (const float*)d_in[2];  const float* b1 = (const float*)d_in[3];
    const float* W2 = (const float*)d_in[4];  const float* b2 = (const float*)d_in[5];
    const float* W3 = (const float*)d_in[6];  const float* b3 = (const float*)d_in[7];
    const float* W4 = (const float*)d_in[8];  const float* b4 = (const float*)d_in[9];
    const float* W5 = (const float*)d_in[10]; const float* b5 = (const float*)d_in[11];
    const float* Wc = (const float*)d_in[12]; const float* bc = (const float*)d_in[13];
    const float* Wm = (const float*)d_in[14]; const float* bm = (const float*)d_in[15];
    float* out = (float*)d_out;

    branch_kernel<<<M_DIM / 16, 256>>>(noise, W1, b1, W2, b2, W3, b3, W4, b4,
                                       W5, b5, Wc, bc, Wm, bm);
    dim3 grid(N_DIM / 1024, M_DIM / 32);
    out_kernel<<<grid, 256>>>(coords, out);
}

// round 10
// speedup vs baseline: 3.1667x; 1.4206x over previous
#include <cuda_runtime.h>
#include <cstdint>

#define M_DIM 4096
#define N_DIM 8192

// Per-row coefficients: out[i,j] = P[i].x*c0_j + P[i].y*c1_j + P[i].z
__device__ __align__(16) float4 g_P[M_DIM];

// ---------------------------------------------------------------------------
// Kernel 1: Branch MLP + fold. 128 blocks x 512 threads (one wave, 1 CTA/SM).
// Block b owns rows [32b, 32b+32): 16 warps x 2 interleaved row chains.
// Fold: W5 + G staged in smem (coalesced), then 99 warp-cooperative dots
// (lane = p lane -> conflict-free LDS).
// Dynamic smem layout (floats):
//   SW1[4096] SW2[1024] SW3[1024] SW4[1024] SB[128] SW5[8192] SG[768]
//   SF[96] SC3[4]
// ---------------------------------------------------------------------------
#define O_SW1 0
#define O_SW2 4096
#define O_SW3 5120
#define O_SW4 6144
#define O_SB  7168
#define O_SW5 7296
#define O_SG  15488
#define O_SF  16256
#define O_SC3 16352
#define BR_SMEM ((16356) * 4)

__global__ __launch_bounds__(512) void branch_kernel(
    const float* __restrict__ noise,
    const float* __restrict__ W1, const float* __restrict__ b1,
    const float* __restrict__ W2, const float* __restrict__ b2,
    const float* __restrict__ W3, const float* __restrict__ b3,
    const float* __restrict__ W4, const float* __restrict__ b4,
    const float* __restrict__ W5, const float* __restrict__ b5,
    const float* __restrict__ Wc, const float* __restrict__ bc,
    const float* __restrict__ Wm, const float* __restrict__ bm)
{
    extern __shared__ float sm[];
    int tid  = threadIdx.x;
    int lane = tid & 31;
    int wid  = tid >> 5;

    // ---- coalesced staging of all weights ----
    for (int i = tid; i < 4096; i += 512) sm[O_SW1 + i] = W1[i];
    for (int i = tid; i < 1024; i += 512) {
        sm[O_SW2 + i] = W2[i]; sm[O_SW3 + i] = W3[i]; sm[O_SW4 + i] = W4[i];
    }
    for (int i = tid; i < 8192; i += 512) sm[O_SW5 + i] = W5[i];
    for (int i = tid; i < 512; i += 512)  { }  // (no-op)
    if (tid < 512) {
        sm[O_SG + tid] = Wc[tid];                 // G[0], G[1]
    }
    if (tid < 256) sm[O_SG + 512 + tid] = bc[tid];  // G[2]
    if (tid < 128) {
        int c = tid >> 5, l = tid & 31;
        sm[O_SB + c * 32 + l] = (c == 0) ? b1[l] : (c == 1) ? b2[l]
                              : (c == 2) ? b3[l] : b4[l];
    }
    __syncthreads();

    // ---- fold: 99 warp-cooperative dot products of length 256 ----
    // d < 96: sF[c][k] = W5[k,:] . G[c];  d >= 96: sc3[c] = b5 . G[c] + extra
    for (int d = wid; d < 99; d += 16) {
        float s = 0.f;
        if (d < 96) {
            int c = d >> 5, k = d & 31;
            const float* wr = sm + O_SW5 + k * 256 + lane;
            const float* gr = sm + O_SG + c * 256 + lane;
            #pragma unroll
            for (int t = 0; t < 8; t++) s = fmaf(wr[32 * t], gr[32 * t], s);
        } else {
            int c = d - 96;
            const float* gr = sm + O_SG + c * 256 + lane;
            #pragma unroll
            for (int t = 0; t < 8; t++) s = fmaf(b5[lane + 32 * t], gr[32 * t], s);
        }
        #pragma unroll
        for (int off = 16; off; off >>= 1) s += __shfl_xor_sync(~0u, s, off);
        if (lane == 0) {
            if (d < 96) sm[O_SF + d] = s;
            else {
                int c = d - 96;
                float extra = (c == 0) ? Wm[0] : (c == 1) ? Wm[1] : bm[0];
                sm[O_SC3 + c] = s + extra;
            }
        }
    }
    __syncthreads();

    // ---- MLP: two interleaved rows per warp (16 warps -> 32 rows) ----
    int rowA = blockIdx.x * 32 + wid;
    int rowB = rowA + 16;

    const float* xa = noise + rowA * 128;
    const float* xb = noise + rowB * 128;
    float xa0 = xa[lane], xa1 = xa[lane + 32], xa2 = xa[lane + 64], xa3 = xa[lane + 96];
    float xb0 = xb[lane], xb1 = xb[lane + 32], xb2 = xb[lane + 64], xb3 = xb[lane + 96];

    const float* sW1 = sm + O_SW1;
    const float* sb  = sm + O_SB;

    float aa0 = sb[lane], aa1 = 0.f, aa2 = 0.f, aa3 = 0.f;
    float ba0 = sb[lane], ba1 = 0.f, ba2 = 0.f, ba3 = 0.f;
    #pragma unroll
    for (int k = 0; k < 32; k++) {
        float w0 = sW1[k * 32 + lane];
        float w1 = sW1[(k + 32) * 32 + lane];
        float w2 = sW1[(k + 64) * 32 + lane];
        float w3 = sW1[(k + 96) * 32 + lane];
        aa0 = fmaf(__shfl_sync(~0u, xa0, k), w0, aa0);
        ba0 = fmaf(__shfl_sync(~0u, xb0, k), w0, ba0);
        aa1 = fmaf(__shfl_sync(~0u, xa1, k), w1, aa1);
        ba1 = fmaf(__shfl_sync(~0u, xb1, k), w1, ba1);
        aa2 = fmaf(__shfl_sync(~0u, xa2, k), w2, aa2);
        ba2 = fmaf(__shfl_sync(~0u, xb2, k), w2, ba2);
        aa3 = fmaf(__shfl_sync(~0u, xa3, k), w3, aa3);
        ba3 = fmaf(__shfl_sync(~0u, xb3, k), w3, ba3);
    }
    float hA = tanhf((aa0 + aa1) + (aa2 + aa3));
    float hB = tanhf((ba0 + ba1) + (ba2 + ba3));

    #pragma unroll
    for (int L = 0; L < 3; L++) {
        const float* W = sm + ((L == 0) ? O_SW2 : (L == 1) ? O_SW3 : O_SW4);
        float a = sb[32 * (L + 1) + lane];
        float b = a;
        #pragma unroll
        for (int k = 0; k < 32; k++) {
            float w = W[k * 32 + lane];
            a = fmaf(__shfl_sync(~0u, hA, k), w, a);
            b = fmaf(__shfl_sync(~0u, hB, k), w, b);
        }
        hA = tanhf(a);
        hB = tanhf(b);
    }

    // ---- head: warp-reduce h . F[c] for both rows ----
    float F0 = sm[O_SF + lane], F1 = sm[O_SF + 32 + lane], F2 = sm[O_SF + 64 + lane];
    float pa0 = hA * F0, pa1 = hA * F1, pa2 = hA * F2;
    float pb0 = hB * F0, pb1 = hB * F1, pb2 = hB * F2;
    #pragma unroll
    for (int off = 16; off; off >>= 1) {
        pa0 += __shfl_xor_sync(~0u, pa0, off);
        pa1 += __shfl_xor_sync(~0u, pa1, off);
        pa2 += __shfl_xor_sync(~0u, pa2, off);
        pb0 += __shfl_xor_sync(~0u, pb0, off);
        pb1 += __shfl_xor_sync(~0u, pb1, off);
        pb2 += __shfl_xor_sync(~0u, pb2, off);
    }
    if (lane == 0) {
        float c0 = sm[O_SC3 + 0], c1 = sm[O_SC3 + 1], c2 = sm[O_SC3 + 2];
        g_P[rowA] = make_float4(pa0 + c0, pa1 + c1, pa2 + c2, 0.f);
        g_P[rowB] = make_float4(pb0 + c0, pb1 + c1, pb2 + c2, 0.f);
    }
}

// ---------------------------------------------------------------------------
// Kernel 2: writer (unchanged from R9; measured 23.2us @ ~5.8 TB/s).
// Grid (8, 128) = 1024 blocks x 256 threads.
// ---------------------------------------------------------------------------
__global__ __launch_bounds__(256) void out_kernel(
    const float* __restrict__ coords, float* __restrict__ out)
{
    __shared__ float4 sP[32];
    int tid = threadIdx.x;
    int r0  = blockIdx.y * 32;
    if (tid < 32) sP[tid] = g_P[r0 + tid];

    int j = blockIdx.x * 1024 + tid * 4;
    float4 ca = *(const float4*)(coords + 2 * j);
    float4 cb = *(const float4*)(coords + 2 * j + 4);
    __syncthreads();

    float* orow = out + (size_t)r0 * N_DIM + j;
    #pragma unroll 8
    for (int r = 0; r < 32; r++) {
        float4 P = sP[r];
        float4 v;
        v.x = fmaf(P.x, ca.x, fmaf(P.y, ca.y, P.z));
        v.y = fmaf(P.x, ca.z, fmaf(P.y, ca.w, P.z));
        v.z = fmaf(P.x, cb.x, fmaf(P.y, cb.y, P.z));
        v.w = fmaf(P.x, cb.z, fmaf(P.y, cb.w, P.z));
        *(float4*)(orow + (size_t)r * N_DIM) = v;
    }
}

// ---------------------------------------------------------------------------
extern "C" void kernel_launch(void* const* d_in, const int* in_sizes, int n_in,
                              void* d_out, int out_size) {
    const float* noise  = (const float*)d_in[0];
    const float* coords = (const float*)d_in[1];
    const float* W1 = (const float*)d_in[2];  const float* b1 = (const float*)d_in[3];
    const float* W2 = (const float*)d_in[4];  const float* b2 = (const float*)d_in[5];
    const float* W3 = (const float*)d_in[6];  const float* b3 = (const float*)d_in[7];
    const float* W4 = (const float*)d_in[8];  const float* b4 = (const float*)d_in[9];
    const float* W5 = (const float*)d_in[10]; const float* b5 = (const float*)d_in[11];
    const float* Wc = (const float*)d_in[12]; const float* bc = (const float*)d_in[13];
    const float* Wm = (const float*)d_in[14]; const float* bm = (const float*)d_in[15];
    float* out = (float*)d_out;

    cudaFuncSetAttribute(branch_kernel,
                         cudaFuncAttributeMaxDynamicSharedMemorySize, BR_SMEM);

    branch_kernel<<<M_DIM / 32, 512, BR_SMEM>>>(noise, W1, b1, W2, b2, W3, b3,
                                                W4, b4, W5, b5, Wc, bc, Wm, bm);
    dim3 grid(N_DIM / 1024, M_DIM / 32);
    out_kernel<<<grid, 256>>>(coords, out);
}

// round 11
// speedup vs baseline: 4.2149x; 1.3310x over previous
#include <cuda_runtime.h>
#include <cstdint>

#define M_DIM 4096
#define N_DIM 8192

// Per-row coefficients: out[i,j] = P[i].x*c0_j + P[i].y*c1_j + P[i].z
__device__ __align__(16) float4 g_P[M_DIM];

// ---------------------------------------------------------------------------
// mbarrier / bulk-copy helpers
// ---------------------------------------------------------------------------
__device__ __forceinline__ uint32_t smem_u32(const void* p) {
    uint32_t a;
    asm("{ .reg .u64 t; cvta.to.shared.u64 t, %1; cvt.u32.u64 %0, t; }" : "=r"(a) : "l"(p));
    return a;
}
#define MBARRIER_INIT(addr, cnt) \
    asm volatile("mbarrier.init.shared.b64 [%0], %1;" :: "r"(addr), "r"(cnt) : "memory")
#define MBARRIER_EXPECT_TX(addr, bytes) \
    asm volatile("mbarrier.arrive.expect_tx.shared.b64 _, [%0], %1;" :: "r"(addr), "r"(bytes) : "memory")
#define MBAR_WAIT(addr, parity) do {                                         \
    asm volatile("{\n\t.reg .pred P;\n\t"                                    \
        "W%=:\n\t"                                                           \
        "mbarrier.try_wait.parity.acquire.cta.shared::cta.b64 P, [%0], %1, 0x989680;\n\t" \
        "@P bra.uni D%=;\n\t bra.uni W%=;\n\tD%=:\n\t}"                      \
        :: "r"(addr), "r"(parity) : "memory");                               \
} while (0)
__device__ __forceinline__ void bulk_g2s(uint32_t dst, const void* src, uint32_t bytes,
                                         uint32_t mbar) {
    asm volatile(
        "cp.async.bulk.shared::cluster.global.mbarrier::complete_tx::bytes [%0], [%1], %2, [%3];"
        :: "r"(dst), "l"(src), "r"(bytes), "r"(mbar) : "memory");
}

// ---------------------------------------------------------------------------
// Kernel 1: Branch MLP + fold. 128 blocks x 512 threads (one wave, 1 CTA/SM).
// Prologue: ALL weights staged via cp.async.bulk (TMA engine) + one mbarrier
// -> prologue latency collapses from ~15us of serial LDG to ~1-2us.
// Fold: 99 warp-cooperative dot products (lane = p lane, conflict-free LDS).
// MLP: 16 warps x 2 interleaved row chains -> 32 rows/block.
// Dynamic smem layout (floats):
//   SW1[4096] SW2[1024] SW3[1024] SW4[1024] SB[128] SW5[8192] SG[768]
//   SB5[256] SF[96] SC3[4] MBAR
// ---------------------------------------------------------------------------
#define O_SW1 0
#define O_SW2 4096
#define O_SW3 5120
#define O_SW4 6144
#define O_SB  7168
#define O_SW5 7296
#define O_SG  15488
#define O_SB5 16256
#define O_SF  16512
#define O_SC3 16608
#define O_MB  16612           // mbarrier (2 floats = 8 bytes)
#define BR_SMEM ((16616) * 4)

#define STAGE_BYTES ((4096 + 3 * 1024 + 4 * 32 + 8192 + 768 + 256) * 4)

__global__ __launch_bounds__(512) void branch_kernel(
    const float* __restrict__ noise,
    const float* __restrict__ W1, const float* __restrict__ b1,
    const float* __restrict__ W2, const float* __restrict__ b2,
    const float* __restrict__ W3, const float* __restrict__ b3,
    const float* __restrict__ W4, const float* __restrict__ b4,
    const float* __restrict__ W5, const float* __restrict__ b5,
    const float* __restrict__ Wc, const float* __restrict__ bc,
    const float* __restrict__ Wm, const float* __restrict__ bm)
{
    extern __shared__ __align__(16) float sm[];
    int tid  = threadIdx.x;
    int lane = tid & 31;
    int wid  = tid >> 5;

    uint32_t smb  = smem_u32(sm);
    uint32_t mbar = smb + O_MB * 4;

    // ---- prologue: bulk-stage every weight tensor, one mbarrier ----
    if (tid == 0) {
        MBARRIER_INIT(mbar, 1);
        asm volatile("fence.proxy.async.shared::cta;" ::: "memory");
        MBARRIER_EXPECT_TX(mbar, STAGE_BYTES);
        bulk_g2s(smb + O_SW1 * 4, W1, 4096 * 4, mbar);
        bulk_g2s(smb + O_SW2 * 4, W2, 1024 * 4, mbar);
        bulk_g2s(smb + O_SW3 * 4, W3, 1024 * 4, mbar);
        bulk_g2s(smb + O_SW4 * 4, W4, 1024 * 4, mbar);
        bulk_g2s(smb + (O_SB +  0) * 4, b1, 32 * 4, mbar);
        bulk_g2s(smb + (O_SB + 32) * 4, b2, 32 * 4, mbar);
        bulk_g2s(smb + (O_SB + 64) * 4, b3, 32 * 4, mbar);
        bulk_g2s(smb + (O_SB + 96) * 4, b4, 32 * 4, mbar);
        bulk_g2s(smb + O_SW5 * 4, W5, 8192 * 4, mbar);
        bulk_g2s(smb + O_SG * 4,  Wc, 512 * 4, mbar);       // G[0], G[1]
        bulk_g2s(smb + (O_SG + 512) * 4, bc, 256 * 4, mbar); // G[2]
        bulk_g2s(smb + O_SB5 * 4, b5, 256 * 4, mbar);
    }
    // early: fetch this warp's noise rows while TMA streams weights
    int rowA = blockIdx.x * 32 + wid;
    int rowB = rowA + 16;
    const float* xa = noise + rowA * 128;
    const float* xb = noise + rowB * 128;
    float xa0 = xa[lane], xa1 = xa[lane + 32], xa2 = xa[lane + 64], xa3 = xa[lane + 96];
    float xb0 = xb[lane], xb1 = xb[lane + 32], xb2 = xb[lane + 64], xb3 = xb[lane + 96];

    __syncthreads();          // mbarrier init visible to all
    MBAR_WAIT(mbar, 0);

    // ---- fold: 99 warp-cooperative dot products of length 256 ----
    for (int d = wid; d < 99; d += 16) {
        float s = 0.f;
        if (d < 96) {
            int c = d >> 5, k = d & 31;
            const float* wr = sm + O_SW5 + k * 256 + lane;
            const float* gr = sm + O_SG + c * 256 + lane;
            #pragma unroll
            for (int t = 0; t < 8; t++) s = fmaf(wr[32 * t], gr[32 * t], s);
        } else {
            int c = d - 96;
            const float* gr = sm + O_SG + c * 256 + lane;
            const float* br = sm + O_SB5 + lane;
            #pragma unroll
            for (int t = 0; t < 8; t++) s = fmaf(br[32 * t], gr[32 * t], s);
        }
        #pragma unroll
        for (int off = 16; off; off >>= 1) s += __shfl_xor_sync(~0u, s, off);
        if (lane == 0) {
            if (d < 96) sm[O_SF + d] = s;
            else {
                int c = d - 96;
                float extra = (c == 0) ? Wm[0] : (c == 1) ? Wm[1] : bm[0];
                sm[O_SC3 + c] = s + extra;
            }
        }
    }
    __syncthreads();

    // ---- MLP: two interleaved rows per warp (16 warps -> 32 rows) ----
    const float* sW1 = sm + O_SW1;
    const float* sb  = sm + O_SB;

    float aa0 = sb[lane], aa1 = 0.f, aa2 = 0.f, aa3 = 0.f;
    float ba0 = sb[lane], ba1 = 0.f, ba2 = 0.f, ba3 = 0.f;
    #pragma unroll
    for (int k = 0; k < 32; k++) {
        float w0 = sW1[k * 32 + lane];
        float w1 = sW1[(k + 32) * 32 + lane];
        float w2 = sW1[(k + 64) * 32 + lane];
        float w3 = sW1[(k + 96) * 32 + lane];
        aa0 = fmaf(__shfl_sync(~0u, xa0, k), w0, aa0);
        ba0 = fmaf(__shfl_sync(~0u, xb0, k), w0, ba0);
        aa1 = fmaf(__shfl_sync(~0u, xa1, k), w1, aa1);
        ba1 = fmaf(__shfl_sync(~0u, xb1, k), w1, ba1);
        aa2 = fmaf(__shfl_sync(~0u, xa2, k), w2, aa2);
        ba2 = fmaf(__shfl_sync(~0u, xb2, k), w2, ba2);
        aa3 = fmaf(__shfl_sync(~0u, xa3, k), w3, aa3);
        ba3 = fmaf(__shfl_sync(~0u, xb3, k), w3, ba3);
    }
    float hA = tanhf((aa0 + aa1) + (aa2 + aa3));
    float hB = tanhf((ba0 + ba1) + (ba2 + ba3));

    #pragma unroll
    for (int L = 0; L < 3; L++) {
        const float* W = sm + ((L == 0) ? O_SW2 : (L == 1) ? O_SW3 : O_SW4);
        float a = sb[32 * (L + 1) + lane];
        float b = a;
        #pragma unroll
        for (int k = 0; k < 32; k++) {
            float w = W[k * 32 + lane];
            a = fmaf(__shfl_sync(~0u, hA, k), w, a);
            b = fmaf(__shfl_sync(~0u, hB, k), w, b);
        }
        hA = tanhf(a);
        hB = tanhf(b);
    }

    // ---- head: warp-reduce h . F[c] for both rows ----
    float F0 = sm[O_SF + lane], F1 = sm[O_SF + 32 + lane], F2 = sm[O_SF + 64 + lane];
    float pa0 = hA * F0, pa1 = hA * F1, pa2 = hA * F2;
    float pb0 = hB * F0, pb1 = hB * F1, pb2 = hB * F2;
    #pragma unroll
    for (int off = 16; off; off >>= 1) {
        pa0 += __shfl_xor_sync(~0u, pa0, off);
        pa1 += __shfl_xor_sync(~0u, pa1, off);
        pa2 += __shfl_xor_sync(~0u, pa2, off);
        pb0 += __shfl_xor_sync(~0u, pb0, off);
        pb1 += __shfl_xor_sync(~0u, pb1, off);
        pb2 += __shfl_xor_sync(~0u, pb2, off);
    }
    if (lane == 0) {
        float c0 = sm[O_SC3 + 0], c1 = sm[O_SC3 + 1], c2 = sm[O_SC3 + 2];
        g_P[rowA] = make_float4(pa0 + c0, pa1 + c1, pa2 + c2, 0.f);
        g_P[rowB] = make_float4(pb0 + c0, pb1 + c1, pb2 + c2, 0.f);
    }
}

// ---------------------------------------------------------------------------
// Kernel 2: writer (unchanged; at the effective write wall ~5.6 TB/s).
// Grid (8, 128) = 1024 blocks x 256 threads.
// ---------------------------------------------------------------------------
__global__ __launch_bounds__(256) void out_kernel(
    const float* __restrict__ coords, float* __restrict__ out)
{
    __shared__ float4 sP[32];
    int tid = threadIdx.x;
    int r0  = blockIdx.y * 32;
    if (tid < 32) sP[tid] = g_P[r0 + tid];

    int j = blockIdx.x * 1024 + tid * 4;
    float4 ca = *(const float4*)(coords + 2 * j);
    float4 cb = *(const float4*)(coords + 2 * j + 4);
    __syncthreads();

    float* orow = out + (size_t)r0 * N_DIM + j;
    #pragma unroll 8
    for (int r = 0; r < 32; r++) {
        float4 P = sP[r];
        float4 v;
        v.x = fmaf(P.x, ca.x, fmaf(P.y, ca.y, P.z));
        v.y = fmaf(P.x, ca.z, fmaf(P.y, ca.w, P.z));
        v.z = fmaf(P.x, cb.x, fmaf(P.y, cb.y, P.z));
        v.w = fmaf(P.x, cb.z, fmaf(P.y, cb.w, P.z));
        *(float4*)(orow + (size_t)r * N_DIM) = v;
    }
}

// ---------------------------------------------------------------------------
extern "C" void kernel_launch(void* const* d_in, const int* in_sizes, int n_in,
                              void* d_out, int out_size) {
    const float* noise  = (const float*)d_in[0];
    const float* coords = (const float*)d_in[1];
    const float* W1 = (const float*)d_in[2];  const float* b1 = (const float*)d_in[3];
    const float* W2 = (const float*)d_in[4];  const float* b2 = (const float*)d_in[5];
    const float* W3 = (const float*)d_in[6];  const float* b3 = (const float*)d_in[7];
    const float* W4 = (const float*)d_in[8];  const float* b4 = (const float*)d_in[9];
    const float* W5 = (const float*)d_in[10]; const float* b5 = (const float*)d_in[11];
    const float* Wc = (const float*)d_in[12]; const float* bc = (const float*)d_in[13];
    const float* Wm = (const float*)d_in[14]; const float* bm = (const float*)d_in[15];
    float* out = (float*)d_out;

    cudaFuncSetAttribute(branch_kernel,
                         cudaFuncAttributeMaxDynamicSharedMemorySize, BR_SMEM);

    branch_kernel<<<M_DIM / 32, 512, BR_SMEM>>>(noise, W1, b1, W2, b2, W3, b3,
                                                W4, b4, W5, b5, Wc, bc, Wm, bm);
    dim3 grid(N_DIM / 1024, M_DIM / 32);
    out_kernel<<<grid, 256>>>(coords, out);
}